// round 2
// baseline (speedup 1.0000x reference)
#include <cuda_runtime.h>
#include <cuda_bf16.h>
#include <float.h>

// Problem constants
#define NB   16
#define CDIM 256
#define HW   4096              // 64*64
#define NVEC 65536             // NB*HW
#define NE   1024              // codebook entries
#define LOSS_OFF  16777216
#define IDX_OFF   16777217

// ---------------- scratch (no allocations allowed) ----------------
__device__ float d_ct[CDIM * NE];      // codebook transposed [K=256][N=1024]
__device__ float d_cnorm[NE];
__device__ float d_znorm[NVEC];
__device__ float d_dmin[NVEC];
__device__ int   d_sidx[NVEC];

// ---------------- kernel 1a: codebook row norms ----------------
// Emulate XLA-CPU: sq_k = fl(c_k*c_k); sum sequentially ascending k (no FMA).
__global__ void k_cnorm(const float* __restrict__ cb) {
    int j = blockIdx.x * blockDim.x + threadIdx.x;
    if (j >= NE) return;
    const float* row = cb + (size_t)j * CDIM;
    float s = 0.f;
    for (int k = 0; k < CDIM; ++k) {
        float v = row[k];
        s = __fadd_rn(s, __fmul_rn(v, v));
    }
    d_cnorm[j] = s;
}

// ---------------- kernel 1b: z row norms ----------------
// One thread per vector (b,p); k ascending sequential chain, rounded squares.
__global__ void k_znorm(const float* __restrict__ z) {
    int i = blockIdx.x * blockDim.x + threadIdx.x;   // global vector index
    if (i >= NVEC) return;
    int b = i >> 12;
    int p = i & 4095;
    const float* base = z + ((size_t)b << 20) + p;   // z[b][0][p]
    float s = 0.f;
#pragma unroll 8
    for (int k = 0; k < CDIM; ++k) {
        float v = base[(size_t)k * HW];
        s = __fadd_rn(s, __fmul_rn(v, v));
    }
    d_znorm[i] = s;
}

// ---------------- kernel 1c: transpose codebook to [K][N] ----------------
__global__ void k_transpose(const float* __restrict__ cb) {
    __shared__ float t[32][33];
    int j0 = blockIdx.x * 32;   // codebook row tile
    int k0 = blockIdx.y * 32;   // channel tile
    int x = threadIdx.x, y = threadIdx.y;   // block 32x8
#pragma unroll
    for (int yy = y; yy < 32; yy += 8)
        t[yy][x] = cb[(size_t)(j0 + yy) * CDIM + k0 + x];
    __syncthreads();
#pragma unroll
    for (int yy = y; yy < 32; yy += 8)
        d_ct[(size_t)(k0 + yy) * NE + j0 + x] = t[x][yy];
}

// ---------------- kernel 2: fused GEMM (dot chain) + exact-rounded argmin ---
// Block: 128 rows x full 1024 codebook entries. 256 threads, 8x8 microtile.
// dot accumulated as single FFMA chain in strictly ascending k (Eigen gebp
// emulation); d = fl(fl(znorm + cnorm) - 2*dot); argmin keeps lowest index.
__global__ __launch_bounds__(256, 2)
void k_main(const float* __restrict__ z) {
    __shared__ float zs[32][128];
    __shared__ float cs[32][128];
    __shared__ float cn[128];
    __shared__ float zn[128];

    const int tid = threadIdx.x;
    const int tx = tid & 15;        // N direction
    const int ty = tid >> 4;        // M direction

    const int i0 = blockIdx.x * 128;        // first vector index
    const int b  = i0 >> 12;
    const int p0 = i0 & 4095;
    const float* zb = z + ((size_t)b << 20) + p0;

    if (tid < 128) zn[tid] = d_znorm[i0 + tid];

    float best[8];
    int   bidx[8];
#pragma unroll
    for (int r = 0; r < 8; ++r) { best[r] = FLT_MAX; bidx[r] = 0x7fffffff; }

    for (int nt = 0; nt < 8; ++nt) {
        const int j0 = nt * 128;
        __syncthreads();                       // WAR: prior epilogue read cn
        if (tid < 128) cn[tid] = d_cnorm[j0 + tid];

        float acc[8][8];
#pragma unroll
        for (int r = 0; r < 8; ++r)
#pragma unroll
            for (int c = 0; c < 8; ++c) acc[r][c] = 0.f;

        for (int kc = 0; kc < CDIM; kc += 32) {
            __syncthreads();
#pragma unroll
            for (int t = 0; t < 4; ++t) {
                int s  = tid + t * 256;
                int k  = s >> 5;
                int m4 = s & 31;
                float4 v = *(const float4*)(zb + (size_t)(kc + k) * HW + m4 * 4);
                *(float4*)(&zs[k][m4 * 4]) = v;
                float4 w = *(const float4*)(d_ct + (size_t)(kc + k) * NE + j0 + m4 * 4);
                *(float4*)(&cs[k][m4 * 4]) = w;
            }
            __syncthreads();
#pragma unroll
            for (int k = 0; k < 32; ++k) {        // strictly ascending k
                float a[8], bb[8];
                *(float4*)(a)      = *(const float4*)(&zs[k][ty * 8]);
                *(float4*)(a + 4)  = *(const float4*)(&zs[k][ty * 8 + 4]);
                *(float4*)(bb)     = *(const float4*)(&cs[k][tx * 8]);
                *(float4*)(bb + 4) = *(const float4*)(&cs[k][tx * 8 + 4]);
#pragma unroll
                for (int r = 0; r < 8; ++r)
#pragma unroll
                    for (int c = 0; c < 8; ++c)
                        acc[r][c] = __fmaf_rn(a[r], bb[c], acc[r][c]);
            }
        }

        // epilogue: d = fl(fl(zn + cn) - 2*dot), first-index tie-break
#pragma unroll
        for (int r = 0; r < 8; ++r) {
            float zrow = zn[ty * 8 + r];
            float v = FLT_MAX; int vi = 0x7fffffff;
#pragma unroll
            for (int c = 0; c < 8; ++c) {
                float t1 = __fadd_rn(zrow, cn[tx * 8 + c]);
                float d  = __fadd_rn(t1, -(2.0f * acc[r][c]));  // 2*acc exact
                int   j  = j0 + tx * 8 + c;
                if (d < v) { v = d; vi = j; }     // ascending j: strict keeps first
            }
#pragma unroll
            for (int o = 8; o; o >>= 1) {
                float v2 = __shfl_xor_sync(0xffffffffu, v, o);
                int   i2 = __shfl_xor_sync(0xffffffffu, vi, o);
                if (v2 < v || (v2 == v && i2 < vi)) { v = v2; vi = i2; }
            }
            if (v < best[r] || (v == best[r] && vi < bidx[r])) { best[r] = v; bidx[r] = vi; }
        }
    }

    if (tx == 0) {
#pragma unroll
        for (int r = 0; r < 8; ++r) {
            int row = i0 + ty * 8 + r;
            d_dmin[row] = best[r];
            d_sidx[row] = bidx[r];
        }
    }
}

// ---------------- kernel 3: loss (fp64 accumulate, ref-style final rounding) --
__global__ void k_loss(float* __restrict__ out) {
    __shared__ double sh[1024];
    const int t = threadIdx.x;
    double s = 0.0;
#pragma unroll
    for (int j = 0; j < 64; ++j) s += (double)d_dmin[t + j * 1024];
    sh[t] = s;
    __syncthreads();
#pragma unroll
    for (int o = 512; o; o >>= 1) {
        if (t < o) sh[t] += sh[t + o];
        __syncthreads();
    }
    if (t == 0) {
        float m = (float)(sh[0] / 16777216.0);              // mean (÷2^24 exact)
        out[LOSS_OFF] = __fadd_rn(m, __fmul_rn(0.25f, m));  // L + 0.25*L
    }
}

// ---------------- kernel 4: gather codebook rows -> output + indices ---------
__global__ void k_gather(const float* __restrict__ cb, float* __restrict__ out) {
    __shared__ float sm[32][257];
    __shared__ int js[32];
    const int i0 = blockIdx.x * 32;
    const int b  = i0 >> 12;
    const int p0 = i0 & 4095;
    const int t  = threadIdx.x;

    if (t < 32) js[t] = d_sidx[i0 + t];
    __syncthreads();

#pragma unroll
    for (int s = t; s < 32 * 256; s += 256) {
        int row = s >> 8, col = s & 255;
        sm[row][col] = cb[(size_t)js[row] * CDIM + col];
    }
    __syncthreads();

    float* ob = out + ((size_t)b << 20) + p0;
#pragma unroll
    for (int c0 = 0; c0 < 256; c0 += 8) {
        int c = c0 + (t >> 5);
        int p = t & 31;
        ob[((size_t)c << 12) + p] = sm[p][c];
    }

    if (t < 32) out[IDX_OFF + i0 + t] = (float)js[t];
}

// ---------------- launch ----------------
extern "C" void kernel_launch(void* const* d_in, const int* in_sizes, int n_in,
                              void* d_out, int out_size) {
    const float* z  = (const float*)d_in[0];
    const float* cb = (const float*)d_in[1];
    float* out = (float*)d_out;

    k_cnorm<<<4, 256>>>(cb);
    k_znorm<<<NVEC / 256, 256>>>(z);
    k_transpose<<<dim3(NE / 32, CDIM / 32), dim3(32, 8)>>>(cb);
    k_main<<<NVEC / 128, 256>>>(z);
    k_loss<<<1, 1024>>>(out);
    k_gather<<<NVEC / 32, 256>>>(cb, out);
}

// round 4
// speedup vs baseline: 1.0296x; 1.0296x over previous
#include <cuda_runtime.h>
#include <cuda_bf16.h>
#include <cstdint>
#include <float.h>

// Problem constants
#define CDIM 256
#define HW   4096              // 64*64
#define NVEC 65536             // 16*4096
#define NE   1024
#define LOSS_OFF  16777216
#define IDX_OFF   16777217

// ---------------- scratch ----------------
__device__ float d_ct[CDIM * NE];      // codebook transposed [K=256][N=1024]
__device__ float d_cnorm[NE];
__device__ float d_dmin[NVEC];
__device__ int   d_sidx[NVEC];

// ---------------- cp.async helpers ----------------
__device__ __forceinline__ void cp_async16(unsigned int smem, const void* g) {
    asm volatile("cp.async.cg.shared.global [%0], [%1], 16;\n" :: "r"(smem), "l"(g));
}
__device__ __forceinline__ void cp_commit() {
    asm volatile("cp.async.commit_group;\n" ::: "memory");
}
template<int N>
__device__ __forceinline__ void cp_wait() {
    asm volatile("cp.async.wait_group %0;\n" :: "n"(N) : "memory");
}

// ---------------- kernel 1a: codebook row norms (exact sequential chain) ----
__global__ void k_cnorm(const float* __restrict__ cb) {
    int j = blockIdx.x * blockDim.x + threadIdx.x;
    if (j >= NE) return;
    const float* row = cb + (size_t)j * CDIM;
    float s = 0.f;
    for (int k = 0; k < CDIM; ++k) {
        float v = row[k];
        s = __fadd_rn(s, __fmul_rn(v, v));
    }
    d_cnorm[j] = s;
}

// ---------------- kernel 1b: transpose codebook to [K][N] ----------------
__global__ void k_transpose(const float* __restrict__ cb) {
    __shared__ float t[32][33];
    int j0 = blockIdx.x * 32;
    int k0 = blockIdx.y * 32;
    int x = threadIdx.x, y = threadIdx.y;   // 32x8
#pragma unroll
    for (int yy = y; yy < 32; yy += 8)
        t[yy][x] = cb[(size_t)(j0 + yy) * CDIM + k0 + x];
    __syncthreads();
#pragma unroll
    for (int yy = y; yy < 32; yy += 8)
        d_ct[(size_t)(k0 + yy) * NE + j0 + x] = t[x][yy];
}

// ---------------- compute helper: one 16-K chunk ----------------
template<bool ZN>
__device__ __forceinline__ void compute_chunk(
    const float* __restrict__ zsb, const float* __restrict__ csb,
    float acc[8][8], float* znacc, int tx, int ty)
{
#pragma unroll 8
    for (int k = 0; k < 16; ++k) {             // strictly ascending k
        float a[8], bb[8];
        *(float4*)(a)      = *(const float4*)(zsb + k * 128 + ty * 8);
        *(float4*)(a + 4)  = *(const float4*)(zsb + k * 128 + ty * 8 + 4);
        *(float4*)(bb)     = *(const float4*)(csb + k * 128 + tx * 8);
        *(float4*)(bb + 4) = *(const float4*)(csb + k * 128 + tx * 8 + 4);
        if (ZN) {
#pragma unroll
            for (int r = 0; r < 8; ++r)
                znacc[r] = __fadd_rn(znacc[r], __fmul_rn(a[r], a[r]));
        }
#pragma unroll
        for (int r = 0; r < 8; ++r)
#pragma unroll
            for (int c = 0; c < 8; ++c)
                acc[r][c] = __fmaf_rn(a[r], bb[c], acc[r][c]);
    }
}

// ---------------- kernel 2: fused GEMM + znorm + exact-rounded argmin ------
// 128 rows x 1024 entries per block; 256 threads, 8x8 microtile;
// cp.async double-buffered 16-K chunks; dot = single FFMA chain ascending k;
// d = fl(fl(znorm + cnorm) - 2*dot); argmin keeps lowest index.
__global__ __launch_bounds__(256, 2)
void k_main(const float* __restrict__ z) {
    __shared__ __align__(16) float zs[2][16 * 128];
    __shared__ __align__(16) float cs[2][16 * 128];
    __shared__ float cn[128];

    const int tid = threadIdx.x;
    const int tx = tid & 15;
    const int ty = tid >> 4;

    const int i0 = blockIdx.x * 128;
    const int b  = i0 >> 12;
    const int p0 = i0 & 4095;
    const float* zb = z + ((size_t)b << 20) + p0;

    // per-thread cp.async slots: k in {kl, kl+8}, column m4*4
    const int kl = tid >> 5;          // 0..7
    const int m4 = tid & 31;

    const unsigned int zs0 = (unsigned int)__cvta_generic_to_shared(&zs[0][0]);
    const unsigned int cs0 = (unsigned int)__cvta_generic_to_shared(&cs[0][0]);
    const unsigned int soff = (unsigned int)((kl * 128 + m4 * 4) * 4);
    const unsigned int soff8 = soff + 8 * 128 * 4;
    const unsigned int BUFB = 16 * 128 * 4;   // 8KB per buffer

    float znacc[8];
    float best[8];
    int   bidx[8];
#pragma unroll
    for (int r = 0; r < 8; ++r) { znacc[r] = 0.f; best[r] = FLT_MAX; bidx[r] = 0x7fffffff; }

    for (int nt = 0; nt < 8; ++nt) {
        const int j0 = nt * 128;
        __syncthreads();                      // buffers + cn free for reuse
        if (tid < 128) cn[tid] = d_cnorm[j0 + tid];

        // prologue: chunk 0 -> buffer 0
        {
            const float* zp = zb + (size_t)kl * HW + m4 * 4;
            const float* cp = d_ct + (size_t)kl * NE + j0 + m4 * 4;
            cp_async16(zs0 + soff,  zp);
            cp_async16(zs0 + soff8, zp + (size_t)8 * HW);
            cp_async16(cs0 + soff,  cp);
            cp_async16(cs0 + soff8, cp + (size_t)8 * NE);
            cp_commit();
        }

        float acc[8][8];
#pragma unroll
        for (int r = 0; r < 8; ++r)
#pragma unroll
            for (int c = 0; c < 8; ++c) acc[r][c] = 0.f;

        for (int ch = 0; ch < 16; ++ch) {
            cp_wait<0>();
            __syncthreads();                  // chunk ch ready; prior compute done
            if (ch < 15) {                    // issue chunk ch+1 into other buffer
                const int kc = (ch + 1) * 16;
                const unsigned int bo = ((ch + 1) & 1) * BUFB;
                const float* zp = zb + (size_t)(kc + kl) * HW + m4 * 4;
                const float* cp = d_ct + (size_t)(kc + kl) * NE + j0 + m4 * 4;
                cp_async16(zs0 + bo + soff,  zp);
                cp_async16(zs0 + bo + soff8, zp + (size_t)8 * HW);
                cp_async16(cs0 + bo + soff,  cp);
                cp_async16(cs0 + bo + soff8, cp + (size_t)8 * NE);
                cp_commit();
            }
            const float* zsb = &zs[ch & 1][0];
            const float* csb = &cs[ch & 1][0];
            if (nt == 0)
                compute_chunk<true>(zsb, csb, acc, znacc, tx, ty);
            else
                compute_chunk<false>(zsb, csb, acc, znacc, tx, ty);
        }

        // epilogue: d = fl(fl(zn + cn) - 2*dot), first-index tie-break
#pragma unroll
        for (int r = 0; r < 8; ++r) {
            float zrow = znacc[r];
            float v = FLT_MAX; int vi = 0x7fffffff;
#pragma unroll
            for (int c = 0; c < 8; ++c) {
                float t1 = __fadd_rn(zrow, cn[tx * 8 + c]);
                float d  = __fadd_rn(t1, -(2.0f * acc[r][c]));   // 2*acc exact
                int   j  = j0 + tx * 8 + c;
                if (d < v) { v = d; vi = j; }    // ascending j: strict keeps first
            }
#pragma unroll
            for (int o = 8; o; o >>= 1) {
                float v2 = __shfl_xor_sync(0xffffffffu, v, o);
                int   i2 = __shfl_xor_sync(0xffffffffu, vi, o);
                if (v2 < v || (v2 == v && i2 < vi)) { v = v2; vi = i2; }
            }
            if (v < best[r] || (v == best[r] && vi < bidx[r])) { best[r] = v; bidx[r] = vi; }
        }
    }

    if (tx == 0) {
#pragma unroll
        for (int r = 0; r < 8; ++r) {
            int row = i0 + ty * 8 + r;
            d_dmin[row] = best[r];
            d_sidx[row] = bidx[r];
        }
    }
}

// ---------------- kernel 3: loss (fp64 accumulate, ref-style final rounding) --
__global__ void k_loss(float* __restrict__ out) {
    __shared__ double sh[1024];
    const int t = threadIdx.x;
    double s = 0.0;
#pragma unroll
    for (int j = 0; j < 64; ++j) s += (double)d_dmin[t + j * 1024];
    sh[t] = s;
    __syncthreads();
#pragma unroll
    for (int o = 512; o; o >>= 1) {
        if (t < o) sh[t] += sh[t + o];
        __syncthreads();
    }
    if (t == 0) {
        float m = (float)(sh[0] / 16777216.0);
        out[LOSS_OFF] = __fadd_rn(m, __fmul_rn(0.25f, m));
    }
}

// ---------------- kernel 4: gather codebook rows -> output + indices ---------
__global__ void k_gather(const float* __restrict__ cb, float* __restrict__ out) {
    __shared__ float sm[32][257];
    __shared__ int js[32];
    const int i0 = blockIdx.x * 32;
    const int b  = i0 >> 12;
    const int p0 = i0 & 4095;
    const int t  = threadIdx.x;

    if (t < 32) js[t] = d_sidx[i0 + t];
    __syncthreads();

#pragma unroll
    for (int s = t; s < 32 * 256; s += 256) {
        int row = s >> 8, col = s & 255;
        sm[row][col] = cb[(size_t)js[row] * CDIM + col];
    }
    __syncthreads();

    float* ob = out + ((size_t)b << 20) + p0;
#pragma unroll
    for (int c0 = 0; c0 < 256; c0 += 8) {
        int c = c0 + (t >> 5);
        int p = t & 31;
        ob[((size_t)c << 12) + p] = sm[p][c];
    }

    if (t < 32) out[IDX_OFF + i0 + t] = (float)js[t];
}

// ---------------- launch ----------------
extern "C" void kernel_launch(void* const* d_in, const int* in_sizes, int n_in,
                              void* d_out, int out_size) {
    const float* z  = (const float*)d_in[0];
    const float* cb = (const float*)d_in[1];
    float* out = (float*)d_out;

    k_cnorm<<<4, 256>>>(cb);
    k_transpose<<<dim3(NE / 32, CDIM / 32), dim3(32, 8)>>>(cb);
    k_main<<<NVEC / 128, 256>>>(z);
    k_loss<<<1, 1024>>>(out);
    k_gather<<<NVEC / 32, 256>>>(cb, out);
}